// round 1
// baseline (speedup 1.0000x reference)
#include <cuda_runtime.h>
#include <cuda_bf16.h>
#include <math.h>

// Problem constants
#define BB    4
#define T1    2048
#define TKV   8
#define NN    64
#define DIMM  1024
#define DLL   1024
#define DHH   64
#define HH    8
#define INNER 512            // H*DH
#define DFF   4096
#define JJ    512            // TKV*NN
#define M1    8192           // B*T1
#define MKV   2048           // B*TKV*NN

#define NEGMASK (-3.402823466e+38f)

// ---------------- scratch (static device globals; no allocations) ----------------
__device__ float g_lnq[(size_t)M1 * DIMM];
__device__ float g_q  [(size_t)M1 * INNER];
__device__ float g_kv [(size_t)MKV * 1024];
__device__ float g_att[(size_t)M1 * INNER];
__device__ float g_x  [(size_t)M1 * DIMM];
__device__ float g_lnx[(size_t)M1 * DIMM];
__device__ float g_h  [(size_t)M1 * DFF];
__device__ int   g_mask_mode;   // 0 = bool8, 1 = int32, 2 = float32

// ---------------- mask dtype detection ----------------
__global__ void detect_mask_kernel(const unsigned char* __restrict__ am) {
    __shared__ int f1, f23;
    if (threadIdx.x == 0) { f1 = 0; f23 = 0; }
    __syncthreads();
    // scan 256 KB of the attention mask buffer (attn_mask has >=4M elements)
    for (int i = threadIdx.x * 4; i < 262144; i += 1024) {
        if (am[i + 1]) atomicOr(&f1, 1);
        if (am[i + 2] | am[i + 3]) atomicOr(&f23, 1);
    }
    __syncthreads();
    if (threadIdx.x == 0) g_mask_mode = f1 ? 0 : (f23 ? 2 : 1);
}

__device__ __forceinline__ bool read_mask(const void* p, size_t idx, int mode) {
    if (mode == 0) return ((const unsigned char*)p)[idx] != 0;
    if (mode == 1) return ((const int*)p)[idx] != 0;
    return ((const float*)p)[idx] != 0.0f;
}

// ---------------- LayerNorm: one block per row of 1024 ----------------
__global__ void __launch_bounds__(256) ln_kernel(
    const float* __restrict__ X, float* __restrict__ Y,
    const float* __restrict__ gg, const float* __restrict__ bb)
{
    int row = blockIdx.x;
    const float* x = X + (size_t)row * DIMM;
    float* y = Y + (size_t)row * DIMM;
    int tid = threadIdx.x;

    float vals[4];
    float s = 0.f, sq = 0.f;
#pragma unroll
    for (int k = 0; k < 4; k++) {
        float v = x[tid + k * 256];
        vals[k] = v; s += v; sq += v * v;
    }
#pragma unroll
    for (int o = 16; o; o >>= 1) {
        s  += __shfl_xor_sync(0xffffffffu, s, o);
        sq += __shfl_xor_sync(0xffffffffu, sq, o);
    }
    __shared__ float rs[8], rq[8];
    __shared__ float mu_s, inv_s;
    int w = tid >> 5, lane = tid & 31;
    if (lane == 0) { rs[w] = s; rq[w] = sq; }
    __syncthreads();
    if (tid == 0) {
        float S = 0.f, Q = 0.f;
        for (int i = 0; i < 8; i++) { S += rs[i]; Q += rq[i]; }
        float mu = S * (1.0f / DIMM);
        float var = Q * (1.0f / DIMM) - mu * mu;
        mu_s = mu; inv_s = rsqrtf(var + 1e-5f);
    }
    __syncthreads();
    float mu = mu_s, inv = inv_s;
#pragma unroll
    for (int k = 0; k < 4; k++) {
        int c = tid + k * 256;
        y[c] = (vals[k] - mu) * inv * gg[c] + bb[c];
    }
}

// ---------------- SGEMM 128x128x8, 256 threads, 8x8 per thread ----------------
// epi 0: C = acc*scale
// epi 1: C = acc*tanh(gate[0]) + addv
// epi 2: C = gelu_exact(acc)
__global__ void __launch_bounds__(256) sgemm128(
    const float* __restrict__ A, const float* __restrict__ Bm, float* __restrict__ C,
    int M, int N, int K,
    const float* __restrict__ addv, const float* __restrict__ gate,
    float scale, int epi)
{
    __shared__ float As[8][128];
    __shared__ float Bs[8][128];

    int tid = threadIdx.x;
    int tx = tid & 15, ty = tid >> 4;
    int bx = blockIdx.x, by = blockIdx.y;

    const int arow = tid >> 1, ac4 = (tid & 1) << 2;
    const int brow = tid >> 5, bc4 = (tid & 31) << 2;

    float acc[8][8];
#pragma unroll
    for (int i = 0; i < 8; i++)
#pragma unroll
        for (int j = 0; j < 8; j++) acc[i][j] = 0.f;

    const float* Aptr = A + (size_t)(by * 128 + arow) * K + ac4;
    const float* Bptr = Bm + (size_t)brow * N + (size_t)bx * 128 + bc4;

    for (int k0 = 0; k0 < K; k0 += 8) {
        float4 av = *(const float4*)(Aptr + k0);
        As[ac4 + 0][arow] = av.x;
        As[ac4 + 1][arow] = av.y;
        As[ac4 + 2][arow] = av.z;
        As[ac4 + 3][arow] = av.w;
        float4 bv = *(const float4*)(Bptr + (size_t)k0 * N);
        *(float4*)&Bs[brow][bc4] = bv;
        __syncthreads();
#pragma unroll
        for (int kk = 0; kk < 8; kk++) {
            float a[8], b[8];
#pragma unroll
            for (int i = 0; i < 8; i++) a[i] = As[kk][ty * 8 + i];
#pragma unroll
            for (int j = 0; j < 8; j++) b[j] = Bs[kk][tx * 8 + j];
#pragma unroll
            for (int i = 0; i < 8; i++)
#pragma unroll
                for (int j = 0; j < 8; j++)
                    acc[i][j] = fmaf(a[i], b[j], acc[i][j]);
        }
        __syncthreads();
    }

    float g = (epi == 1) ? tanhf(gate[0]) : 0.f;
    const size_t col0 = (size_t)bx * 128 + tx * 8;
#pragma unroll
    for (int i = 0; i < 8; i++) {
        size_t row = (size_t)by * 128 + ty * 8 + i;
        size_t off = row * (size_t)N + col0;
        float v[8];
#pragma unroll
        for (int j = 0; j < 8; j++) {
            float t = acc[i][j];
            if (epi == 0) {
                t *= scale;
            } else if (epi == 1) {
                t = fmaf(t, g, addv[off + j]);
            } else {
                t = 0.5f * t * (1.0f + erff(t * 0.70710678118654752f));
            }
            v[j] = t;
        }
        *(float4*)(C + off)     = make_float4(v[0], v[1], v[2], v[3]);
        *(float4*)(C + off + 4) = make_float4(v[4], v[5], v[6], v[7]);
    }
}

// ---------------- Attention: 8 queries per block, one (b,h) per blockIdx.y ----------------
// Q: (B,T1,INNER) scaled; KV: (B,J,1024) with k = cols [h*64, h*64+64), v = cols [512+h*64, ...)
__global__ void __launch_bounds__(256) attn_kernel(
    const float* __restrict__ Q, const float* __restrict__ KV,
    const void* __restrict__ amask, const void* __restrict__ kvmask,
    const float* __restrict__ qmask, float* __restrict__ O)
{
    __shared__ float qs[8][64];
    __shared__ float kt[64][65];
    __shared__ float sims[8][512];

    int it = blockIdx.x;               // query tile (0..255)
    int bh = blockIdx.y;               // b*H + h (0..31)
    int b = bh >> 3, h = bh & 7;
    int i0g = it * 8;
    int tid = threadIdx.x;
    int mode = g_mask_mode;

    // load Q rows
    for (int idx = tid; idx < 8 * 64; idx += 256) {
        int i = idx >> 6, d = idx & 63;
        qs[i][d] = Q[((size_t)(b * T1 + i0g + i)) * INNER + h * 64 + d];
    }

    // ---- phase 2: sim = q @ k^T with masks ----
    {
        int j = tid & 63;
        int isub = (tid >> 6) * 2;
        for (int jt = 0; jt < 8; jt++) {
            __syncthreads();  // qs ready (first iter) / kt consumers done (later iters)
            for (int idx = tid; idx < 64 * 64; idx += 256) {
                int r = idx >> 6, d = idx & 63;
                kt[r][d] = KV[((size_t)(b * JJ) + jt * 64 + r) * 1024 + h * 64 + d];
            }
            __syncthreads();
            float acc0 = 0.f, acc1 = 0.f;
#pragma unroll
            for (int d = 0; d < 64; d++) {
                float kd = kt[j][d];
                acc0 = fmaf(kd, qs[isub][d], acc0);
                acc1 = fmaf(kd, qs[isub + 1][d], acc1);
            }
            int jg = jt * 64 + j;
            bool kvm = read_mask(kvmask, (size_t)b * JJ + jg, mode);
            bool a0 = kvm && read_mask(amask, ((size_t)(b * T1 + i0g + isub))     * JJ + jg, mode);
            bool a1 = kvm && read_mask(amask, ((size_t)(b * T1 + i0g + isub + 1)) * JJ + jg, mode);
            sims[isub][jg]     = a0 ? acc0 : NEGMASK;
            sims[isub + 1][jg] = a1 ? acc1 : NEGMASK;
        }
    }
    __syncthreads();

    // ---- phase 3: softmax per row (one warp per row) ----
    {
        int w = tid >> 5, lane = tid & 31;
        float* srow = sims[w];
        float v[16];
        float mx = -INFINITY;
#pragma unroll
        for (int k = 0; k < 16; k++) {
            v[k] = srow[lane + k * 32];
            mx = fmaxf(mx, v[k]);
        }
#pragma unroll
        for (int o = 16; o; o >>= 1) mx = fmaxf(mx, __shfl_xor_sync(0xffffffffu, mx, o));
        float sum = 0.f;
#pragma unroll
        for (int k = 0; k < 16; k++) { v[k] = expf(v[k] - mx); sum += v[k]; }
#pragma unroll
        for (int o = 16; o; o >>= 1) sum += __shfl_xor_sync(0xffffffffu, sum, o);
        float inv = 1.0f / sum;
#pragma unroll
        for (int k = 0; k < 16; k++) srow[lane + k * 32] = v[k] * inv;
    }

    // ---- phase 4: out = attn @ v ----
    {
        int d = tid & 63;
        int i2 = (tid >> 6) * 2;
        float o0 = 0.f, o1 = 0.f;
        for (int jt = 0; jt < 8; jt++) {
            __syncthreads();  // previous kt consumers done / softmax done (first iter)
            for (int idx = tid; idx < 64 * 64; idx += 256) {
                int r = idx >> 6, dd = idx & 63;
                kt[r][dd] = KV[((size_t)(b * JJ) + jt * 64 + r) * 1024 + INNER + h * 64 + dd];
            }
            __syncthreads();
#pragma unroll
            for (int r = 0; r < 64; r++) {
                float vv = kt[r][d];
                o0 = fmaf(sims[i2][jt * 64 + r], vv, o0);
                o1 = fmaf(sims[i2 + 1][jt * 64 + r], vv, o1);
            }
        }
        float qm0 = qmask[(size_t)b * T1 + i0g + i2];
        float qm1 = qmask[(size_t)b * T1 + i0g + i2 + 1];
        O[((size_t)(b * T1 + i0g + i2))     * INNER + h * 64 + d] = o0 * qm0;
        O[((size_t)(b * T1 + i0g + i2 + 1)) * INNER + h * 64 + d] = o1 * qm1;
    }
}

// ---------------- launch ----------------
extern "C" void kernel_launch(void* const* d_in, const int* in_sizes, int n_in,
                              void* d_out, int out_size)
{
    const float* qo        = (const float*)d_in[0];
    const float* kvo       = (const float*)d_in[1];
    const void*  amask     = d_in[2];
    const float* qmask     = (const float*)d_in[3];
    const void*  kvmask    = d_in[4];
    const float* ln_g      = (const float*)d_in[5];
    const float* ln_b      = (const float*)d_in[6];
    const float* Wq        = (const float*)d_in[7];
    const float* Wkv       = (const float*)d_in[8];
    const float* Wout      = (const float*)d_in[9];
    const float* attn_gate = (const float*)d_in[10];
    const float* ff_ln_g   = (const float*)d_in[11];
    const float* ff_ln_b   = (const float*)d_in[12];
    const float* W1        = (const float*)d_in[13];
    const float* W2        = (const float*)d_in[14];
    const float* ff_gate   = (const float*)d_in[15];
    float* out = (float*)d_out;

    float *lnq, *q, *kv, *att, *x, *lnx, *h;
    cudaGetSymbolAddress((void**)&lnq, g_lnq);
    cudaGetSymbolAddress((void**)&q,   g_q);
    cudaGetSymbolAddress((void**)&kv,  g_kv);
    cudaGetSymbolAddress((void**)&att, g_att);
    cudaGetSymbolAddress((void**)&x,   g_x);
    cudaGetSymbolAddress((void**)&lnx, g_lnx);
    cudaGetSymbolAddress((void**)&h,   g_h);

    detect_mask_kernel<<<1, 256>>>((const unsigned char*)amask);

    // q = LN(qo) @ Wq * DH^-0.5
    ln_kernel<<<M1, 256>>>(qo, lnq, ln_g, ln_b);
    sgemm128<<<dim3(INNER / 128, M1 / 128), 256>>>(lnq, Wq, q, M1, INNER, DIMM,
                                                   nullptr, nullptr, 0.125f, 0);
    // kv = kvo_flat @ Wkv
    sgemm128<<<dim3(1024 / 128, MKV / 128), 256>>>(kvo, Wkv, kv, MKV, 1024, DLL,
                                                   nullptr, nullptr, 1.0f, 0);
    // attention
    attn_kernel<<<dim3(T1 / 8, BB * HH), 256>>>(q, kv, amask, kvmask, qmask, att);

    // x = att @ Wout * tanh(attn_gate) + qo
    sgemm128<<<dim3(DIMM / 128, M1 / 128), 256>>>(att, Wout, x, M1, DIMM, INNER,
                                                  qo, attn_gate, 1.0f, 1);
    // h = gelu(LN(x) @ W1)
    ln_kernel<<<M1, 256>>>(x, lnx, ff_ln_g, ff_ln_b);
    sgemm128<<<dim3(DFF / 128, M1 / 128), 256>>>(lnx, W1, h, M1, DFF, DIMM,
                                                 nullptr, nullptr, 1.0f, 2);
    // out = h @ W2 * tanh(ff_gate) + x
    sgemm128<<<dim3(DIMM / 128, M1 / 128), 256>>>(h, W2, out, M1, DIMM, DFF,
                                                  x, ff_gate, 1.0f, 1);
}

// round 2
// speedup vs baseline: 3.2502x; 3.2502x over previous
#include <cuda_runtime.h>
#include <cuda_bf16.h>
#include <math.h>
#include <stdint.h>

// Problem constants
#define BB    4
#define T1    2048
#define TKV   8
#define NN    64
#define DIMM  1024
#define DLL   1024
#define DHH   64
#define HH    8
#define INNER 512            // H*DH
#define DFF   4096
#define JJ    512            // TKV*NN
#define M1    8192           // B*T1
#define MKV   2048           // B*TKV*NN

#define NEGMASK (-3.402823466e+38f)

// ---------------- scratch (static device globals; no allocations) ----------------
__device__ float g_lnq[(size_t)M1 * DIMM];
__device__ float g_q  [(size_t)M1 * INNER];
__device__ float g_kv [(size_t)MKV * 1024];
__device__ float g_att[(size_t)M1 * INNER];
__device__ float g_x  [(size_t)M1 * DIMM];
__device__ float g_lnx[(size_t)M1 * DIMM];
__device__ float g_h  [(size_t)M1 * DFF];
__device__ int   g_mask_mode;   // 0 = bool8, 1 = int32, 2 = float32

// ---------------- mask dtype detection ----------------
__global__ void detect_mask_kernel(const unsigned char* __restrict__ am) {
    __shared__ int f1, f23;
    if (threadIdx.x == 0) { f1 = 0; f23 = 0; }
    __syncthreads();
    for (int i = threadIdx.x * 4; i < 262144; i += 1024) {
        if (am[i + 1]) atomicOr(&f1, 1);
        if (am[i + 2] | am[i + 3]) atomicOr(&f23, 1);
    }
    __syncthreads();
    if (threadIdx.x == 0) g_mask_mode = f1 ? 0 : (f23 ? 2 : 1);
}

__device__ __forceinline__ bool read_mask(const void* p, size_t idx, int mode) {
    if (mode == 0) return ((const unsigned char*)p)[idx] != 0;
    if (mode == 1) return ((const int*)p)[idx] != 0;
    return ((const float*)p)[idx] != 0.0f;
}

// ---------------- LayerNorm: one block per row of 1024 ----------------
__global__ void __launch_bounds__(256) ln_kernel(
    const float* __restrict__ X, float* __restrict__ Y,
    const float* __restrict__ gg, const float* __restrict__ bb)
{
    int row = blockIdx.x;
    const float* x = X + (size_t)row * DIMM;
    float* y = Y + (size_t)row * DIMM;
    int tid = threadIdx.x;

    float vals[4];
    float s = 0.f, sq = 0.f;
#pragma unroll
    for (int k = 0; k < 4; k++) {
        float v = x[tid + k * 256];
        vals[k] = v; s += v; sq += v * v;
    }
#pragma unroll
    for (int o = 16; o; o >>= 1) {
        s  += __shfl_xor_sync(0xffffffffu, s, o);
        sq += __shfl_xor_sync(0xffffffffu, sq, o);
    }
    __shared__ float rs[8], rq[8];
    __shared__ float mu_s, inv_s;
    int w = tid >> 5, lane = tid & 31;
    if (lane == 0) { rs[w] = s; rq[w] = sq; }
    __syncthreads();
    if (tid == 0) {
        float S = 0.f, Q = 0.f;
        for (int i = 0; i < 8; i++) { S += rs[i]; Q += rq[i]; }
        float mu = S * (1.0f / DIMM);
        float var = Q * (1.0f / DIMM) - mu * mu;
        mu_s = mu; inv_s = rsqrtf(var + 1e-5f);
    }
    __syncthreads();
    float mu = mu_s, inv = inv_s;
#pragma unroll
    for (int k = 0; k < 4; k++) {
        int c = tid + k * 256;
        y[c] = (vals[k] - mu) * inv * gg[c] + bb[c];
    }
}

// ---------------- TF32 tensor-core GEMM: 128x128x32 tiles ----------------
// 256 threads = 8 warps (4 m x 2 n), warp tile 32x64, mma.m16n8k8.tf32
// epi 0: C = acc*scale
// epi 1: C = acc*tanh(gate[0]) + addv
// epi 2: C = gelu_exact(acc)

__device__ __forceinline__ uint32_t f2tf(float f) {
    uint32_t u;
    asm("cvt.rna.tf32.f32 %0, %1;" : "=r"(u) : "f"(f));
    return u;
}

__device__ __forceinline__ void mma_tf32(
    float& d0, float& d1, float& d2, float& d3,
    uint32_t a0, uint32_t a1, uint32_t a2, uint32_t a3,
    uint32_t b0, uint32_t b1)
{
    asm volatile(
        "mma.sync.aligned.m16n8k8.row.col.f32.tf32.tf32.f32 "
        "{%0,%1,%2,%3},{%4,%5,%6,%7},{%8,%9},{%0,%1,%2,%3};"
        : "+f"(d0), "+f"(d1), "+f"(d2), "+f"(d3)
        : "r"(a0), "r"(a1), "r"(a2), "r"(a3), "r"(b0), "r"(b1));
}

#define AS_STRIDE 36    // 32 + 4 : bank = 4m+k  -> conflict-free fragment reads
#define BS_STRIDE 136   // 128 + 8: bank = 8k+n  -> conflict-free fragment reads

__global__ void __launch_bounds__(256, 2) tgemm(
    const float* __restrict__ A, const float* __restrict__ Bm, float* __restrict__ C,
    int M, int N, int K,
    const float* __restrict__ addv, const float* __restrict__ gate,
    float scale, int epi)
{
    __shared__ float As[128 * AS_STRIDE];   // [m][k]
    __shared__ float Bs[32 * BS_STRIDE];    // [k][n]

    int tid  = threadIdx.x;
    int lane = tid & 31, wid = tid >> 5;
    int wm = (wid & 3) * 32;       // warp row base within tile
    int wn = (wid >> 2) * 64;      // warp col base within tile
    int gr = lane >> 2;            // group row 0..7
    int tg = lane & 3;             // thread-in-group 0..3

    // A loader: rows a_row + 32*i, k-quad a_k4
    int a_row = tid >> 3;              // 0..31
    int a_k4  = (tid & 7) << 2;        // 0..28
    const float* Ag = A + (size_t)(blockIdx.y * 128 + a_row) * K + a_k4;

    // B loader: k rows b_k + 8*i, n-quad b_n4
    int b_k  = tid >> 5;               // 0..7
    int b_n4 = (tid & 31) << 2;        // 0..124
    const float* Bg = Bm + (size_t)b_k * N + blockIdx.x * 128 + b_n4;

    float acc[2][8][4];
#pragma unroll
    for (int i = 0; i < 2; i++)
#pragma unroll
        for (int j = 0; j < 8; j++)
#pragma unroll
            for (int c = 0; c < 4; c++) acc[i][j][c] = 0.f;

    for (int k0 = 0; k0 < K; k0 += 32) {
        __syncthreads();
        // stage A (128x32) with tf32 rounding
#pragma unroll
        for (int i = 0; i < 4; i++) {
            float4 v = *(const float4*)(Ag + (size_t)(32 * i) * K + k0);
            uint4 u = make_uint4(f2tf(v.x), f2tf(v.y), f2tf(v.z), f2tf(v.w));
            *(uint4*)&As[(a_row + 32 * i) * AS_STRIDE + a_k4] = u;
        }
        // stage B (32x128) with tf32 rounding
#pragma unroll
        for (int i = 0; i < 4; i++) {
            float4 v = *(const float4*)(Bg + (size_t)(k0 + 8 * i) * N);
            uint4 u = make_uint4(f2tf(v.x), f2tf(v.y), f2tf(v.z), f2tf(v.w));
            *(uint4*)&Bs[(b_k + 8 * i) * BS_STRIDE + b_n4] = u;
        }
        __syncthreads();

#pragma unroll
        for (int ks = 0; ks < 4; ks++) {
            int kk = ks * 8 + tg;
            uint32_t a[2][4];
#pragma unroll
            for (int mf = 0; mf < 2; mf++) {
                int r = wm + mf * 16 + gr;
                a[mf][0] = __float_as_uint(As[r * AS_STRIDE + kk]);
                a[mf][1] = __float_as_uint(As[(r + 8) * AS_STRIDE + kk]);
                a[mf][2] = __float_as_uint(As[r * AS_STRIDE + kk + 4]);
                a[mf][3] = __float_as_uint(As[(r + 8) * AS_STRIDE + kk + 4]);
            }
#pragma unroll
            for (int nf = 0; nf < 8; nf++) {
                int cn = wn + nf * 8 + gr;
                uint32_t b0 = __float_as_uint(Bs[(ks * 8 + tg) * BS_STRIDE + cn]);
                uint32_t b1 = __float_as_uint(Bs[(ks * 8 + tg + 4) * BS_STRIDE + cn]);
                mma_tf32(acc[0][nf][0], acc[0][nf][1], acc[0][nf][2], acc[0][nf][3],
                         a[0][0], a[0][1], a[0][2], a[0][3], b0, b1);
                mma_tf32(acc[1][nf][0], acc[1][nf][1], acc[1][nf][2], acc[1][nf][3],
                         a[1][0], a[1][1], a[1][2], a[1][3], b0, b1);
            }
        }
    }

    // epilogue
    float g = (epi == 1) ? tanhf(gate[0]) : 0.f;
#pragma unroll
    for (int mf = 0; mf < 2; mf++) {
#pragma unroll
        for (int half = 0; half < 2; half++) {
            size_t row = (size_t)blockIdx.y * 128 + wm + mf * 16 + gr + half * 8;
#pragma unroll
            for (int nf = 0; nf < 8; nf++) {
                size_t col = (size_t)blockIdx.x * 128 + wn + nf * 8 + tg * 2;
                size_t off = row * (size_t)N + col;
                float v0 = acc[mf][nf][half * 2 + 0];
                float v1 = acc[mf][nf][half * 2 + 1];
                if (epi == 0) {
                    v0 *= scale; v1 *= scale;
                } else if (epi == 1) {
                    float2 ad = *(const float2*)(addv + off);
                    v0 = fmaf(v0, g, ad.x);
                    v1 = fmaf(v1, g, ad.y);
                } else {
                    v0 = 0.5f * v0 * (1.0f + erff(v0 * 0.70710678118654752f));
                    v1 = 0.5f * v1 * (1.0f + erff(v1 * 0.70710678118654752f));
                }
                *(float2*)(C + off) = make_float2(v0, v1);
            }
        }
    }
}

// ---------------- Attention: 8 queries per block, one (b,h) per blockIdx.y ----------------
__global__ void __launch_bounds__(256) attn_kernel(
    const float* __restrict__ Q, const float* __restrict__ KV,
    const void* __restrict__ amask, const void* __restrict__ kvmask,
    const float* __restrict__ qmask, float* __restrict__ O)
{
    __shared__ float qs[8][64];
    __shared__ float kt[64][65];
    __shared__ float sims[8][512];

    int it = blockIdx.x;               // query tile (0..255)
    int bh = blockIdx.y;               // b*H + h (0..31)
    int b = bh >> 3, h = bh & 7;
    int i0g = it * 8;
    int tid = threadIdx.x;
    int mode = g_mask_mode;

    for (int idx = tid; idx < 8 * 64; idx += 256) {
        int i = idx >> 6, d = idx & 63;
        qs[i][d] = Q[((size_t)(b * T1 + i0g + i)) * INNER + h * 64 + d];
    }

    // sim = q @ k^T with masks
    {
        int j = tid & 63;
        int isub = (tid >> 6) * 2;
        for (int jt = 0; jt < 8; jt++) {
            __syncthreads();
            for (int idx = tid; idx < 64 * 64; idx += 256) {
                int r = idx >> 6, d = idx & 63;
                kt[r][d] = KV[((size_t)(b * JJ) + jt * 64 + r) * 1024 + h * 64 + d];
            }
            __syncthreads();
            float acc0 = 0.f, acc1 = 0.f;
#pragma unroll
            for (int d = 0; d < 64; d++) {
                float kd = kt[j][d];
                acc0 = fmaf(kd, qs[isub][d], acc0);
                acc1 = fmaf(kd, qs[isub + 1][d], acc1);
            }
            int jg = jt * 64 + j;
            bool kvm = read_mask(kvmask, (size_t)b * JJ + jg, mode);
            bool a0 = kvm && read_mask(amask, ((size_t)(b * T1 + i0g + isub))     * JJ + jg, mode);
            bool a1 = kvm && read_mask(amask, ((size_t)(b * T1 + i0g + isub + 1)) * JJ + jg, mode);
            sims[isub][jg]     = a0 ? acc0 : NEGMASK;
            sims[isub + 1][jg] = a1 ? acc1 : NEGMASK;
        }
    }
    __syncthreads();

    // softmax per row (one warp per row)
    {
        int w = tid >> 5, lane = tid & 31;
        float* srow = sims[w];
        float v[16];
        float mx = -INFINITY;
#pragma unroll
        for (int k = 0; k < 16; k++) {
            v[k] = srow[lane + k * 32];
            mx = fmaxf(mx, v[k]);
        }
#pragma unroll
        for (int o = 16; o; o >>= 1) mx = fmaxf(mx, __shfl_xor_sync(0xffffffffu, mx, o));
        float sum = 0.f;
#pragma unroll
        for (int k = 0; k < 16; k++) { v[k] = expf(v[k] - mx); sum += v[k]; }
#pragma unroll
        for (int o = 16; o; o >>= 1) sum += __shfl_xor_sync(0xffffffffu, sum, o);
        float inv = 1.0f / sum;
#pragma unroll
        for (int k = 0; k < 16; k++) srow[lane + k * 32] = v[k] * inv;
    }

    // out = attn @ v
    {
        int d = tid & 63;
        int i2 = (tid >> 6) * 2;
        float o0 = 0.f, o1 = 0.f;
        for (int jt = 0; jt < 8; jt++) {
            __syncthreads();
            for (int idx = tid; idx < 64 * 64; idx += 256) {
                int r = idx >> 6, dd = idx & 63;
                kt[r][dd] = KV[((size_t)(b * JJ) + jt * 64 + r) * 1024 + INNER + h * 64 + dd];
            }
            __syncthreads();
#pragma unroll
            for (int r = 0; r < 64; r++) {
                float vv = kt[r][d];
                o0 = fmaf(sims[i2][jt * 64 + r], vv, o0);
                o1 = fmaf(sims[i2 + 1][jt * 64 + r], vv, o1);
            }
        }
        float qm0 = qmask[(size_t)b * T1 + i0g + i2];
        float qm1 = qmask[(size_t)b * T1 + i0g + i2 + 1];
        O[((size_t)(b * T1 + i0g + i2))     * INNER + h * 64 + d] = o0 * qm0;
        O[((size_t)(b * T1 + i0g + i2 + 1)) * INNER + h * 64 + d] = o1 * qm1;
    }
}

// ---------------- launch ----------------
extern "C" void kernel_launch(void* const* d_in, const int* in_sizes, int n_in,
                              void* d_out, int out_size)
{
    const float* qo        = (const float*)d_in[0];
    const float* kvo       = (const float*)d_in[1];
    const void*  amask     = d_in[2];
    const float* qmask     = (const float*)d_in[3];
    const void*  kvmask    = d_in[4];
    const float* ln_g      = (const float*)d_in[5];
    const float* ln_b      = (const float*)d_in[6];
    const float* Wq        = (const float*)d_in[7];
    const float* Wkv       = (const float*)d_in[8];
    const float* Wout      = (const float*)d_in[9];
    const float* attn_gate = (const float*)d_in[10];
    const float* ff_ln_g   = (const float*)d_in[11];
    const float* ff_ln_b   = (const float*)d_in[12];
    const float* W1        = (const float*)d_in[13];
    const float* W2        = (const float*)d_in[14];
    const float* ff_gate   = (const float*)d_in[15];
    float* out = (float*)d_out;

    float *lnq, *q, *kv, *att, *x, *lnx, *h;
    cudaGetSymbolAddress((void**)&lnq, g_lnq);
    cudaGetSymbolAddress((void**)&q,   g_q);
    cudaGetSymbolAddress((void**)&kv,  g_kv);
    cudaGetSymbolAddress((void**)&att, g_att);
    cudaGetSymbolAddress((void**)&x,   g_x);
    cudaGetSymbolAddress((void**)&lnx, g_lnx);
    cudaGetSymbolAddress((void**)&h,   g_h);

    detect_mask_kernel<<<1, 256>>>((const unsigned char*)amask);

    // q = LN(qo) @ Wq * DH^-0.5
    ln_kernel<<<M1, 256>>>(qo, lnq, ln_g, ln_b);
    tgemm<<<dim3(INNER / 128, M1 / 128), 256>>>(lnq, Wq, q, M1, INNER, DIMM,
                                                nullptr, nullptr, 0.125f, 0);
    // kv = kvo_flat @ Wkv
    tgemm<<<dim3(1024 / 128, MKV / 128), 256>>>(kvo, Wkv, kv, MKV, 1024, DLL,
                                                nullptr, nullptr, 1.0f, 0);
    // attention
    attn_kernel<<<dim3(T1 / 8, BB * HH), 256>>>(q, kv, amask, kvmask, qmask, att);

    // x = att @ Wout * tanh(attn_gate) + qo
    tgemm<<<dim3(DIMM / 128, M1 / 128), 256>>>(att, Wout, x, M1, DIMM, INNER,
                                               qo, attn_gate, 1.0f, 1);
    // h = gelu(LN(x) @ W1)
    ln_kernel<<<M1, 256>>>(x, lnx, ff_ln_g, ff_ln_b);
    tgemm<<<dim3(DFF / 128, M1 / 128), 256>>>(lnx, W1, h, M1, DFF, DIMM,
                                              nullptr, nullptr, 1.0f, 2);
    // out = h @ W2 * tanh(ff_gate) + x
    tgemm<<<dim3(DIMM / 128, M1 / 128), 256>>>(h, W2, out, M1, DIMM, DFF,
                                               x, ff_gate, 1.0f, 1);
}